// round 1
// baseline (speedup 1.0000x reference)
#include <cuda_runtime.h>
#include <cuda_bf16.h>

// RMSNorm over last axis: x[4, 8192, 2048] fp32, weight[2048] fp32.
// out = x * rsqrt(mean(x^2, axis=-1) + 1e-6) * weight
//
// One block per row. 256 threads * 8 floats (2x float4) = 2048 cols.
// Single read of x into registers, block-reduce sum of squares, scale, write.
// HBM-bound: 537 MB total traffic -> ~85-95 us at ~6.3 TB/s effective.

#define NCOLS 2048
#define THREADS 256
#define EPSF 1e-6f

__global__ __launch_bounds__(THREADS)
void rmsnorm_kernel(const float* __restrict__ x,
                    const float* __restrict__ w,
                    float* __restrict__ out)
{
    const long long row = blockIdx.x;
    const float* xr = x + row * (long long)NCOLS;
    float* outr = out + row * (long long)NCOLS;

    const int tid = threadIdx.x;

    // Two float4 loads per thread, covering cols [tid*4, tid*4+3] and
    // [1024 + tid*4, 1024 + tid*4 + 3]. Front-batched for MLP.
    const float4 v0 = reinterpret_cast<const float4*>(xr)[tid];
    const float4 v1 = reinterpret_cast<const float4*>(xr)[tid + THREADS];

    // Sum of squares (fp32 accumulate; 2048 elems -> rel err far below 1e-3)
    float ss = v0.x * v0.x;
    ss = fmaf(v0.y, v0.y, ss);
    ss = fmaf(v0.z, v0.z, ss);
    ss = fmaf(v0.w, v0.w, ss);
    ss = fmaf(v1.x, v1.x, ss);
    ss = fmaf(v1.y, v1.y, ss);
    ss = fmaf(v1.z, v1.z, ss);
    ss = fmaf(v1.w, v1.w, ss);

    // Warp reduction
    #pragma unroll
    for (int off = 16; off > 0; off >>= 1)
        ss += __shfl_xor_sync(0xFFFFFFFFu, ss, off);

    // Cross-warp reduction (8 warps)
    __shared__ float warp_sums[THREADS / 32];
    __shared__ float inv_rms_sh;
    const int warp = tid >> 5;
    const int lane = tid & 31;
    if (lane == 0) warp_sums[warp] = ss;
    __syncthreads();

    if (warp == 0) {
        float s = (lane < THREADS / 32) ? warp_sums[lane] : 0.0f;
        #pragma unroll
        for (int off = 4; off > 0; off >>= 1)
            s += __shfl_xor_sync(0xFFFFFFFFu, s, off);
        if (lane == 0)
            inv_rms_sh = rsqrtf(s * (1.0f / (float)NCOLS) + EPSF);
    }
    __syncthreads();

    const float inv_rms = inv_rms_sh;

    // Weight (8 KB, L2-resident after first rows)
    const float4 w0 = reinterpret_cast<const float4*>(w)[tid];
    const float4 w1 = reinterpret_cast<const float4*>(w)[tid + THREADS];

    float4 o0, o1;
    o0.x = v0.x * inv_rms * w0.x;
    o0.y = v0.y * inv_rms * w0.y;
    o0.z = v0.z * inv_rms * w0.z;
    o0.w = v0.w * inv_rms * w0.w;
    o1.x = v1.x * inv_rms * w1.x;
    o1.y = v1.y * inv_rms * w1.y;
    o1.z = v1.z * inv_rms * w1.z;
    o1.w = v1.w * inv_rms * w1.w;

    reinterpret_cast<float4*>(outr)[tid] = o0;
    reinterpret_cast<float4*>(outr)[tid + THREADS] = o1;
}

extern "C" void kernel_launch(void* const* d_in, const int* in_sizes, int n_in,
                              void* d_out, int out_size)
{
    const float* x = (const float*)d_in[0];   // [4, 8192, 2048]
    const float* w = (const float*)d_in[1];   // [2048]
    float* out = (float*)d_out;

    const int nrows = in_sizes[0] / NCOLS;    // 32768
    rmsnorm_kernel<<<nrows, THREADS>>>(x, w, out);
}